// round 10
// baseline (speedup 1.0000x reference)
#include <cuda_runtime.h>

#define Bb 4
#define Tt 512
#define Cc 128
#define NROWS (Bb * Tt)  // 2048
#define NEG_INF (-1e22f)
#define TI 8

// Q stored transposed: qT[d][global_row]; K row-major.
__device__ float g_qT[Cc * NROWS];
__device__ float g_k[NROWS * Cc];

typedef unsigned long long u64;

// ---- packed f32x2 helpers -------------------------------------------------
__device__ __forceinline__ u64 add2(u64 a, u64 b) {
    u64 s;
    asm("add.rn.f32x2 %0, %1, %2;" : "=l"(s) : "l"(a), "l"(b));
    return s;
}
__device__ __forceinline__ u64 relu2(u64 s) {
    asm("{\n\t"
        ".reg .f32 lo, hi;\n\t"
        "mov.b64 {lo, hi}, %0;\n\t"
        "max.f32 lo, lo, 0f00000000;\n\t"
        "max.f32 hi, hi, 0f00000000;\n\t"
        "mov.b64 %0, {lo, hi};\n\t"
        "}"
        : "+l"(s));
    return s;
}
__device__ __forceinline__ void fma2(u64& acc, u64 a, u64 b) {
    asm("fma.rn.f32x2 %0, %1, %2, %0;" : "+l"(acc) : "l"(a), "l"(b));
}
__device__ __forceinline__ u64 dup2(float w) {
    u64 r;
    asm("mov.b64 %0, {%1, %1};" : "=l"(r) : "f"(w));
    return r;
}
__device__ __forceinline__ u64 pack2(float lo, float hi) {
    u64 r;
    asm("mov.b64 %0, {%1, %2};" : "=l"(r) : "f"(lo), "f"(hi));
    return r;
}
__device__ __forceinline__ float lo2(u64 a) { return __uint_as_float((unsigned)a); }
__device__ __forceinline__ float hi2(u64 a) { return __uint_as_float((unsigned)(a >> 32)); }

// ---------------------------------------------------------------------------
// Kernel 1: Q/K projection (R4 structure). Grid (64, 2): y=0 Q (transposed
// store), y=1 K (row-major). Block = 32 rows x 128 cols; 256 threads:
// threads 0..127 cols for row-half 0... (thread = 1 col x 32 rows via 2 halves)
// ---------------------------------------------------------------------------
__global__ void __launch_bounds__(256) qk_kernel(const float* __restrict__ x,
                                                 const float* __restrict__ WQ,
                                                 const float* __restrict__ WK) {
    __shared__ float4 xs[32 * 32];  // 32 rows x 128 floats
    const int tid  = threadIdx.x;
    const int row0 = blockIdx.x * 32;
    const float* W = blockIdx.y ? WK : WQ;

    // cooperative coalesced load of the 32-row x tile
#pragma unroll
    for (int t = 0; t < 4; t++) {
        int f4 = tid + 256 * t;  // 0..1023
        int r  = f4 >> 5, c = f4 & 31;
        xs[f4] = ((const float4*)(x + (size_t)(row0 + r) * Cc))[c];
    }
    __syncthreads();

    const int col = tid & 127;
    const int rh  = tid >> 7;  // 0/1 -> rows rh*16 .. rh*16+15

    float acc[16];
#pragma unroll
    for (int r = 0; r < 16; r++) acc[r] = 0.f;

#pragma unroll 4
    for (int d4 = 0; d4 < 32; d4++) {
        float w0 = W[(4 * d4 + 0) * Cc + col];
        float w1 = W[(4 * d4 + 1) * Cc + col];
        float w2 = W[(4 * d4 + 2) * Cc + col];
        float w3 = W[(4 * d4 + 3) * Cc + col];
#pragma unroll
        for (int r = 0; r < 16; r++) {
            float4 xv = xs[(rh * 16 + r) * 32 + d4];
            acc[r] += xv.x * w0;
            acc[r] += xv.y * w1;
            acc[r] += xv.z * w2;
            acc[r] += xv.w * w3;
        }
    }

    if (blockIdx.y) {
        // K row-major
#pragma unroll
        for (int r = 0; r < 16; r++)
            g_k[(size_t)(row0 + rh * 16 + r) * Cc + col] = acc[r];
    } else {
        // Q transposed: qT[col][row0 + rh*16 + r], float4 over rows
        float* qb = g_qT + (size_t)col * NROWS + row0 + rh * 16;
#pragma unroll
        for (int r4 = 0; r4 < 4; r4++) {
            float4 v = make_float4(acc[4 * r4 + 0], acc[4 * r4 + 1],
                                   acc[4 * r4 + 2], acc[4 * r4 + 3]);
            *(float4*)(qb + 4 * r4) = v;
        }
    }
}

// ---------------------------------------------------------------------------
// Kernel 2 (R6 verbatim): fused score + masked softmax + AV.
// Grid (64, 4), 512 threads.
// smem (u64): ksd [0,1024) | psd [1024,1152) | sc(float) [1152,3200)
//             scd [3200,7296)  (scd reused as AV reduction buffer)
// ---------------------------------------------------------------------------
#define AT_SMEM_U64 7296
#define AT_SMEM_BYTES (AT_SMEM_U64 * 8)

__global__ void __launch_bounds__(512, 2) attn_kernel(const float* __restrict__ x,
                                                      const float* __restrict__ adj,
                                                      const float* __restrict__ p,
                                                      float* __restrict__ out) {
    extern __shared__ u64 asm_u[];
    u64*   ksd = asm_u;                   // [8][128] k duplicated
    u64*   psd = asm_u + 1024;            // [128]    p duplicated
    float* sc  = (float*)(asm_u + 1152);  // [8][512] raw scores
    u64*   scd = asm_u + 3200;            // [8][512] softmax weights dup'd

    const int tid = threadIdx.x;
    const int b   = blockIdx.y;
    const int i0  = blockIdx.x * TI;

    // stage k rows (dup'd) + p (dup'd)
#pragma unroll
    for (int t = 0; t < 2; t++) {
        int idx = tid + 512 * t;  // 0..1023
        int r = idx >> 7, d = idx & 127;
        ksd[r * 128 + d] = dup2(g_k[(size_t)(b * Tt + i0 + r) * Cc + d]);
    }
    if (tid < 128) psd[tid] = dup2(p[tid]);
    __syncthreads();

    // ================= score phase: thread = 2i x 4j, packed over j =========
    {
        const int ig = tid >> 7;         // 0..3 -> rows 2ig, 2ig+1
        const int j0 = (tid & 127) * 4;  // 4 consecutive j's
        const float* qb = g_qT + b * Tt + j0;

        u64 a00 = 0, a01 = 0, a10 = 0, a11 = 0;
        const u64* k0p = ksd + (2 * ig + 0) * 128;
        const u64* k1p = ksd + (2 * ig + 1) * 128;

#pragma unroll 4
        for (int d4 = 0; d4 < 32; d4++) {
#pragma unroll
            for (int e = 0; e < 4; e++) {
                int d = 4 * d4 + e;
                ulonglong2 q = *(const ulonglong2*)(qb + (size_t)d * NROWS);
                u64 pd = psd[d];
                u64 k0 = k0p[d];
                u64 k1 = k1p[d];
                fma2(a00, pd, relu2(add2(q.x, k0)));
                fma2(a01, pd, relu2(add2(q.y, k0)));
                fma2(a10, pd, relu2(add2(q.x, k1)));
                fma2(a11, pd, relu2(add2(q.y, k1)));
            }
        }
        u64* s0 = (u64*)(sc + (2 * ig + 0) * Tt + j0);
        u64* s1 = (u64*)(sc + (2 * ig + 1) * Tt + j0);
        s0[0] = a00; s0[1] = a01;
        s1[0] = a10; s1[1] = a11;
    }
    __syncthreads();

    // ================= masked softmax (warps 0-7, one row each) =============
    const int warp = tid >> 5, lane = tid & 31;
    if (warp < 8) {
        const int    r    = warp;
        const float* arow = adj + ((size_t)(b * Tt) + i0 + r) * Tt;
        float v[16];
        float m = -3.4e38f;
#pragma unroll
        for (int t = 0; t < 16; t++) {
            int   j = lane + 32 * t;
            float s = sc[r * Tt + j];
            s    = (arow[j] > 0.f) ? s : NEG_INF;
            v[t] = s;
            m    = fmaxf(m, s);
        }
#pragma unroll
        for (int o = 16; o; o >>= 1) m = fmaxf(m, __shfl_xor_sync(0xffffffff, m, o));
        float sum = 0.f;
#pragma unroll
        for (int t = 0; t < 16; t++) {
            v[t] = __expf(v[t] - m);
            sum += v[t];
        }
#pragma unroll
        for (int o = 16; o; o >>= 1) sum += __shfl_xor_sync(0xffffffff, sum, o);
        float inv = 1.f / sum;
#pragma unroll
        for (int t = 0; t < 16; t++)
            scd[r * Tt + lane + 32 * t] = dup2(v[t] * inv);
    }
    __syncthreads();

    // ================= AV: warps = 8 jq x 2 dq; thread = 8i x 2d ===========
    const int jq = warp >> 1;  // 0..7 -> 64 j's
    const int dq = warp & 1;   // 0/1 -> d half
    const int d0 = dq * 64 + 2 * lane;

    u64 av[8];
#pragma unroll
    for (int i = 0; i < 8; i++) av[i] = 0ull;

    const float* xb = x + (size_t)(b * Tt) * Cc;
#pragma unroll 4
    for (int jj = 0; jj < 64; jj++) {
        int j  = jq * 64 + jj;
        u64 xv = *(const u64*)(xb + (size_t)j * Cc + d0);
#pragma unroll
        for (int i = 0; i < 8; i++) fma2(av[i], scd[i * Tt + j], xv);
    }
    __syncthreads();

    // reduce over jq through smem (reuse scd region)
    u64* buf = scd;  // 7 * 8 * 64 u64 = 28KB
    if (jq != 0) {
#pragma unroll
        for (int i = 0; i < 8; i++)
            buf[((jq - 1) * 8 + i) * 64 + dq * 32 + lane] = av[i];
    }
    __syncthreads();
    if (jq == 0) {
#pragma unroll
        for (int q = 0; q < 7; q++)
#pragma unroll
            for (int i = 0; i < 8; i++)
                av[i] = add2(av[i], buf[(q * 8 + i) * 64 + dq * 32 + lane]);
#pragma unroll
        for (int i = 0; i < 8; i++)
            *(u64*)(out + (size_t)(b * Tt + i0 + i) * Cc + d0) = av[i];
    }
}

// ---------------------------------------------------------------------------
extern "C" void kernel_launch(void* const* d_in, const int* in_sizes, int n_in,
                              void* d_out, int out_size) {
    const float* x   = (const float*)d_in[0];
    const float* adj = (const float*)d_in[1];
    const float* WQ  = (const float*)d_in[2];
    const float* WK  = (const float*)d_in[3];
    const float* p   = (const float*)d_in[4];
    float*       out = (float*)d_out;

    qk_kernel<<<dim3(NROWS / 32, 2), 256>>>(x, WQ, WK);

    cudaFuncSetAttribute(attn_kernel, cudaFuncAttributeMaxDynamicSharedMemorySize,
                         AT_SMEM_BYTES);
    attn_kernel<<<dim3(Tt / TI, Bb), 512, AT_SMEM_BYTES>>>(x, adj, p, out);
}

// round 11
// speedup vs baseline: 1.0409x; 1.0409x over previous
#include <cuda_runtime.h>

#define Bb 4
#define Tt 512
#define Cc 128
#define NROWS (Bb * Tt)  // 2048
#define NEG_INF (-1e22f)
#define TI 8

// Q stored transposed: qT[d][global_row]; K row-major.
__device__ float g_qT[Cc * NROWS];
__device__ float g_k[NROWS * Cc];

typedef unsigned long long u64;

// ---- packed f32x2 helpers -------------------------------------------------
__device__ __forceinline__ u64 add2(u64 a, u64 b) {
    u64 s;
    asm("add.rn.f32x2 %0, %1, %2;" : "=l"(s) : "l"(a), "l"(b));
    return s;
}
__device__ __forceinline__ u64 relu2(u64 s) {
    asm("{\n\t"
        ".reg .f32 lo, hi;\n\t"
        "mov.b64 {lo, hi}, %0;\n\t"
        "max.f32 lo, lo, 0f00000000;\n\t"
        "max.f32 hi, hi, 0f00000000;\n\t"
        "mov.b64 %0, {lo, hi};\n\t"
        "}"
        : "+l"(s));
    return s;
}
__device__ __forceinline__ void fma2(u64& acc, u64 a, u64 b) {
    asm("fma.rn.f32x2 %0, %1, %2, %0;" : "+l"(acc) : "l"(a), "l"(b));
}
__device__ __forceinline__ u64 dup2(float w) {
    u64 r;
    asm("mov.b64 %0, {%1, %1};" : "=l"(r) : "f"(w));
    return r;
}
__device__ __forceinline__ float lo2(u64 a) { return __uint_as_float((unsigned)a); }
__device__ __forceinline__ float hi2(u64 a) { return __uint_as_float((unsigned)(a >> 32)); }

// ---------------------------------------------------------------------------
// Kernel 1: Q/K projection — R4 geometry. Grid (NROWS/16 = 128, 2):
// y=0 -> Q (transposed store), y=1 -> K (row-major).
// Block 256 threads: col = tid&127, row-half rh = tid>>7 (8 rows each).
// ---------------------------------------------------------------------------
__global__ void __launch_bounds__(256) qk_kernel(const float* __restrict__ x,
                                                 const float* __restrict__ WQ,
                                                 const float* __restrict__ WK) {
    __shared__ float4 xs[16 * 32];  // 16 rows x 128 floats
    const int tid  = threadIdx.x;
    const int row0 = blockIdx.x * 16;
    const float* W = blockIdx.y ? WK : WQ;

#pragma unroll
    for (int t = 0; t < 2; t++) {
        int f4 = tid + 256 * t;  // 0..511
        int r = f4 >> 5, c = f4 & 31;
        xs[f4] = ((const float4*)(x + (size_t)(row0 + r) * Cc))[c];
    }
    __syncthreads();

    const int col = tid & 127;
    const int rh  = tid >> 7;  // 0/1 -> rows rh*8 .. rh*8+7

    float acc[8];
#pragma unroll
    for (int r = 0; r < 8; r++) acc[r] = 0.f;

#pragma unroll 4
    for (int d4 = 0; d4 < 32; d4++) {
        float w0 = W[(4 * d4 + 0) * Cc + col];
        float w1 = W[(4 * d4 + 1) * Cc + col];
        float w2 = W[(4 * d4 + 2) * Cc + col];
        float w3 = W[(4 * d4 + 3) * Cc + col];
#pragma unroll
        for (int r = 0; r < 8; r++) {
            float4 xv = xs[(rh * 8 + r) * 32 + d4];
            acc[r] += xv.x * w0;
            acc[r] += xv.y * w1;
            acc[r] += xv.z * w2;
            acc[r] += xv.w * w3;
        }
    }

    if (blockIdx.y) {
        // K row-major
#pragma unroll
        for (int r = 0; r < 8; r++)
            g_k[(size_t)(row0 + rh * 8 + r) * Cc + col] = acc[r];
    } else {
        // Q transposed: rows contiguous per thread -> 2 STG.128
        float* qb = g_qT + (size_t)col * NROWS + row0 + rh * 8;
        *(float4*)(qb + 0) = make_float4(acc[0], acc[1], acc[2], acc[3]);
        *(float4*)(qb + 4) = make_float4(acc[4], acc[5], acc[6], acc[7]);
    }
}

// ---------------------------------------------------------------------------
// Kernel 2: fused score + masked softmax + AV. Grid (64, 4), 512 threads.
// Score loop processes dims in PAIRS: p/k0/k1 fetched as LDS.128 broadcasts.
// smem (u64): ksd [0,1024) | psd [1024,1152) | sc(float) [1152,3200)
//             scd [3200,7296)  (scd reused as AV reduction buffer)
// ---------------------------------------------------------------------------
#define AT_SMEM_U64 7296
#define AT_SMEM_BYTES (AT_SMEM_U64 * 8)

__global__ void __launch_bounds__(512, 2) attn_kernel(const float* __restrict__ x,
                                                      const float* __restrict__ adj,
                                                      const float* __restrict__ p,
                                                      float* __restrict__ out) {
    extern __shared__ u64 asm_u[];
    u64*   ksd = asm_u;                   // [8][128] k duplicated
    u64*   psd = asm_u + 1024;            // [128]    p duplicated
    float* sc  = (float*)(asm_u + 1152);  // [8][512] raw scores
    u64*   scd = asm_u + 3200;            // [8][512] softmax weights dup'd

    const int tid = threadIdx.x;
    const int b   = blockIdx.y;
    const int i0  = blockIdx.x * TI;

    // stage k rows (dup'd) + p (dup'd)
#pragma unroll
    for (int t = 0; t < 2; t++) {
        int idx = tid + 512 * t;  // 0..1023
        int r = idx >> 7, d = idx & 127;
        ksd[r * 128 + d] = dup2(g_k[(size_t)(b * Tt + i0 + r) * Cc + d]);
    }
    if (tid < 128) psd[tid] = dup2(p[tid]);
    __syncthreads();

    // ================= score phase: thread = 2i x 4j, dim pairs =============
    {
        const int ig = tid >> 7;         // 0..3 -> rows 2ig, 2ig+1
        const int j0 = (tid & 127) * 4;  // 4 consecutive j's
        const float* qb = g_qT + b * Tt + j0;

        u64 a00 = 0, a01 = 0, a10 = 0, a11 = 0;
        const u64* k0p = ksd + (2 * ig + 0) * 128;
        const u64* k1p = ksd + (2 * ig + 1) * 128;

#pragma unroll 4
        for (int d2 = 0; d2 < 64; d2++) {
            const int d = 2 * d2;
            ulonglong2 qa = *(const ulonglong2*)(qb + (size_t)d * NROWS);
            ulonglong2 qc = *(const ulonglong2*)(qb + (size_t)(d + 1) * NROWS);
            ulonglong2 pd = *(const ulonglong2*)(psd + d);
            ulonglong2 k0 = *(const ulonglong2*)(k0p + d);
            ulonglong2 k1 = *(const ulonglong2*)(k1p + d);

            fma2(a00, pd.x, relu2(add2(qa.x, k0.x)));
            fma2(a01, pd.x, relu2(add2(qa.y, k0.x)));
            fma2(a10, pd.x, relu2(add2(qa.x, k1.x)));
            fma2(a11, pd.x, relu2(add2(qa.y, k1.x)));
            fma2(a00, pd.y, relu2(add2(qc.x, k0.y)));
            fma2(a01, pd.y, relu2(add2(qc.y, k0.y)));
            fma2(a10, pd.y, relu2(add2(qc.x, k1.y)));
            fma2(a11, pd.y, relu2(add2(qc.y, k1.y)));
        }
        u64* s0 = (u64*)(sc + (2 * ig + 0) * Tt + j0);
        u64* s1 = (u64*)(sc + (2 * ig + 1) * Tt + j0);
        s0[0] = a00; s0[1] = a01;
        s1[0] = a10; s1[1] = a11;
    }
    __syncthreads();

    // ================= masked softmax (warps 0-7, one row each) =============
    const int warp = tid >> 5, lane = tid & 31;
    if (warp < 8) {
        const int    r    = warp;
        const float* arow = adj + ((size_t)(b * Tt) + i0 + r) * Tt;
        float v[16];
        float m = -3.4e38f;
#pragma unroll
        for (int t = 0; t < 16; t++) {
            int   j = lane + 32 * t;
            float s = sc[r * Tt + j];
            s    = (arow[j] > 0.f) ? s : NEG_INF;
            v[t] = s;
            m    = fmaxf(m, s);
        }
#pragma unroll
        for (int o = 16; o; o >>= 1) m = fmaxf(m, __shfl_xor_sync(0xffffffff, m, o));
        float sum = 0.f;
#pragma unroll
        for (int t = 0; t < 16; t++) {
            v[t] = __expf(v[t] - m);
            sum += v[t];
        }
#pragma unroll
        for (int o = 16; o; o >>= 1) sum += __shfl_xor_sync(0xffffffff, sum, o);
        float inv = 1.f / sum;
#pragma unroll
        for (int t = 0; t < 16; t++)
            scd[r * Tt + lane + 32 * t] = dup2(v[t] * inv);
    }
    __syncthreads();

    // ================= AV: warps = 8 jq x 2 dq; thread = 8i x 2d ===========
    const int jq = warp >> 1;  // 0..7 -> 64 j's
    const int dq = warp & 1;   // 0/1 -> d half
    const int d0 = dq * 64 + 2 * lane;

    u64 av[8];
#pragma unroll
    for (int i = 0; i < 8; i++) av[i] = 0ull;

    const float* xb = x + (size_t)(b * Tt) * Cc;
#pragma unroll 4
    for (int jj = 0; jj < 64; jj++) {
        int j  = jq * 64 + jj;
        u64 xv = *(const u64*)(xb + (size_t)j * Cc + d0);
#pragma unroll
        for (int i = 0; i < 8; i++) fma2(av[i], scd[i * Tt + j], xv);
    }
    __syncthreads();

    // reduce over jq through smem (reuse scd region)
    u64* buf = scd;  // 7 * 8 * 64 u64 = 28KB
    if (jq != 0) {
#pragma unroll
        for (int i = 0; i < 8; i++)
            buf[((jq - 1) * 8 + i) * 64 + dq * 32 + lane] = av[i];
    }
    __syncthreads();
    if (jq == 0) {
#pragma unroll
        for (int q = 0; q < 7; q++)
#pragma unroll
            for (int i = 0; i < 8; i++)
                av[i] = add2(av[i], buf[(q * 8 + i) * 64 + dq * 32 + lane]);
#pragma unroll
        for (int i = 0; i < 8; i++)
            *(u64*)(out + (size_t)(b * Tt + i0 + i) * Cc + d0) = av[i];
    }
}

// ---------------------------------------------------------------------------
extern "C" void kernel_launch(void* const* d_in, const int* in_sizes, int n_in,
                              void* d_out, int out_size) {
    const float* x   = (const float*)d_in[0];
    const float* adj = (const float*)d_in[1];
    const float* WQ  = (const float*)d_in[2];
    const float* WK  = (const float*)d_in[3];
    const float* p   = (const float*)d_in[4];
    float*       out = (float*)d_out;

    qk_kernel<<<dim3(NROWS / 16, 2), 256>>>(x, WQ, WK);

    cudaFuncSetAttribute(attn_kernel, cudaFuncAttributeMaxDynamicSharedMemorySize,
                         AT_SMEM_BYTES);
    attn_kernel<<<dim3(Tt / TI, Bb), 512, AT_SMEM_BYTES>>>(x, adj, p, out);
}

// round 12
// speedup vs baseline: 1.0486x; 1.0074x over previous
#include <cuda_runtime.h>

#define Bb 4
#define Tt 512
#define Cc 128
#define NROWS (Bb * Tt)  // 2048
#define NEG_INF (-1e22f)
#define TI 8

__device__ float g_q[NROWS * Cc];   // Q row-major (from qk)
__device__ float g_qT[Cc * NROWS];  // Q transposed (from transpose kernel)
__device__ float g_k[NROWS * Cc];   // K row-major

typedef unsigned long long u64;

// ---- packed f32x2 helpers -------------------------------------------------
__device__ __forceinline__ u64 add2(u64 a, u64 b) {
    u64 s;
    asm("add.rn.f32x2 %0, %1, %2;" : "=l"(s) : "l"(a), "l"(b));
    return s;
}
__device__ __forceinline__ u64 relu2(u64 s) {
    asm("{\n\t"
        ".reg .f32 lo, hi;\n\t"
        "mov.b64 {lo, hi}, %0;\n\t"
        "max.f32 lo, lo, 0f00000000;\n\t"
        "max.f32 hi, hi, 0f00000000;\n\t"
        "mov.b64 %0, {lo, hi};\n\t"
        "}"
        : "+l"(s));
    return s;
}
__device__ __forceinline__ void fma2(u64& acc, u64 a, u64 b) {
    asm("fma.rn.f32x2 %0, %1, %2, %0;" : "+l"(acc) : "l"(a), "l"(b));
}
__device__ __forceinline__ u64 dup2(float w) {
    u64 r;
    asm("mov.b64 %0, {%1, %1};" : "=l"(r) : "f"(w));
    return r;
}

// ---------------------------------------------------------------------------
// Kernel 1: Q/K projection — R4 EXACT. Grid (128, 2): y=0 Q, y=1 K, both
// row-major. Block 256 threads.
// ---------------------------------------------------------------------------
__global__ void __launch_bounds__(256) qk_kernel(const float* __restrict__ x,
                                                 const float* __restrict__ WQ,
                                                 const float* __restrict__ WK) {
    __shared__ float4 xs[16 * 32];
    const int tid  = threadIdx.x;
    const int row0 = blockIdx.x * 16;
    const float* W   = blockIdx.y ? WK : WQ;
    float*       OUT = blockIdx.y ? g_k : g_q;

#pragma unroll
    for (int t = 0; t < 2; t++) {
        int f4 = tid + 256 * t;
        int r = f4 >> 5, c = f4 & 31;
        xs[f4] = ((const float4*)(x + (size_t)(row0 + r) * Cc))[c];
    }
    __syncthreads();

    const int col = tid & 127;
    const int rh  = tid >> 7;

    float acc[8];
#pragma unroll
    for (int r = 0; r < 8; r++) acc[r] = 0.f;

#pragma unroll 4
    for (int d4 = 0; d4 < 32; d4++) {
        float w0 = W[(4 * d4 + 0) * Cc + col];
        float w1 = W[(4 * d4 + 1) * Cc + col];
        float w2 = W[(4 * d4 + 2) * Cc + col];
        float w3 = W[(4 * d4 + 3) * Cc + col];
#pragma unroll
        for (int r = 0; r < 8; r++) {
            float4 xv = xs[(rh * 8 + r) * 32 + d4];
            acc[r] += xv.x * w0;
            acc[r] += xv.y * w1;
            acc[r] += xv.z * w2;
            acc[r] += xv.w * w3;
        }
    }
#pragma unroll
    for (int r = 0; r < 8; r++)
        OUT[(size_t)(row0 + rh * 8 + r) * Cc + col] = acc[r];
}

// ---------------------------------------------------------------------------
// Kernel 1b: transpose g_q -> g_qT. 32x32 tiles, both sides coalesced.
// Grid (NROWS/32 = 64, Cc/32 = 4), 256 threads.
// ---------------------------------------------------------------------------
__global__ void __launch_bounds__(256) tr_kernel() {
    __shared__ float tile[32 * 33];
    const int tid  = threadIdx.x;
    const int row0 = blockIdx.x * 32;
    const int d0   = blockIdx.y * 32;

#pragma unroll
    for (int t = 0; t < 4; t++) {
        int idx = tid + 256 * t;  // 0..1023
        int r = idx >> 5, dl = idx & 31;
        tile[dl * 33 + r] = g_q[(size_t)(row0 + r) * Cc + d0 + dl];
    }
    __syncthreads();
#pragma unroll
    for (int t = 0; t < 4; t++) {
        int idx = tid + 256 * t;
        int dl = idx >> 5, rl = idx & 31;
        g_qT[(size_t)(d0 + dl) * NROWS + row0 + rl] = tile[dl * 33 + rl];
    }
}

// ---------------------------------------------------------------------------
// Kernel 2: fused score + masked softmax + AV. Grid (64, 4), 512 threads.
// Score: d split in 2 halves; thread = 2j x 8i over 64 dims.
// smem (u64): kTd [0,1024) | psd [1024,1152) | scpart [1152,5248)
//             scd [5248,10368)  scd[j][10] (8 i dup'd + pad)
//             AV reduce buf reuses scpart.
// ---------------------------------------------------------------------------
#define SCD_STRIDE 10
#define AT_SMEM_U64 (5248 + Tt * SCD_STRIDE)
#define AT_SMEM_BYTES (AT_SMEM_U64 * 8)

__global__ void __launch_bounds__(512, 2) attn_kernel(const float* __restrict__ x,
                                                      const float* __restrict__ adj,
                                                      const float* __restrict__ p,
                                                      float* __restrict__ out) {
    extern __shared__ u64 asm_u[];
    u64*   kTd    = asm_u;           // [128 d][8 i] dup'd k
    u64*   psd    = asm_u + 1024;    // [128] p dup'd
    u64*   scpart = asm_u + 1152;    // [2 dh][8 i][256 jp] u64 partial scores
    u64*   scd    = asm_u + 5248;    // [512 j][10] dup'd weights (8 used)
    float* scpf   = (float*)scpart;  // float view [16][512]

    const int tid = threadIdx.x;
    const int b   = blockIdx.y;
    const int i0  = blockIdx.x * TI;

    // stage kT dup'd + p dup'd
#pragma unroll
    for (int t = 0; t < 2; t++) {
        int idx = tid + 512 * t;  // 0..1023
        int d = idx >> 3, i = idx & 7;
        kTd[d * 8 + i] = dup2(g_k[(size_t)(b * Tt + i0 + i) * Cc + d]);
    }
    if (tid < 128) psd[tid] = dup2(p[tid]);
    __syncthreads();

    // ================= score: thread = 2j x 8i over 64 dims (d-half) ========
    {
        const int dh = tid >> 8;         // 0/1
        const int jt = tid & 255;        // j pair index
        const int j0 = 2 * jt;
        const float* qb = g_qT + b * Tt + j0;

        u64 acc[8];
#pragma unroll
        for (int i = 0; i < 8; i++) acc[i] = 0ull;

        const int dbase = dh * 64;
#pragma unroll 4
        for (int d2 = 0; d2 < 32; d2++) {
            const int d = dbase + 2 * d2;
            u64 qa = *(const u64*)(qb + (size_t)d * NROWS);
            u64 qc = *(const u64*)(qb + (size_t)(d + 1) * NROWS);
            ulonglong2 pd = *(const ulonglong2*)(psd + d);
            ulonglong2 ka01 = *(const ulonglong2*)(kTd + d * 8 + 0);
            ulonglong2 ka23 = *(const ulonglong2*)(kTd + d * 8 + 2);
            ulonglong2 ka45 = *(const ulonglong2*)(kTd + d * 8 + 4);
            ulonglong2 ka67 = *(const ulonglong2*)(kTd + d * 8 + 6);
            ulonglong2 kc01 = *(const ulonglong2*)(kTd + (d + 1) * 8 + 0);
            ulonglong2 kc23 = *(const ulonglong2*)(kTd + (d + 1) * 8 + 2);
            ulonglong2 kc45 = *(const ulonglong2*)(kTd + (d + 1) * 8 + 4);
            ulonglong2 kc67 = *(const ulonglong2*)(kTd + (d + 1) * 8 + 6);

            fma2(acc[0], pd.x, relu2(add2(qa, ka01.x)));
            fma2(acc[1], pd.x, relu2(add2(qa, ka01.y)));
            fma2(acc[2], pd.x, relu2(add2(qa, ka23.x)));
            fma2(acc[3], pd.x, relu2(add2(qa, ka23.y)));
            fma2(acc[4], pd.x, relu2(add2(qa, ka45.x)));
            fma2(acc[5], pd.x, relu2(add2(qa, ka45.y)));
            fma2(acc[6], pd.x, relu2(add2(qa, ka67.x)));
            fma2(acc[7], pd.x, relu2(add2(qa, ka67.y)));

            fma2(acc[0], pd.y, relu2(add2(qc, kc01.x)));
            fma2(acc[1], pd.y, relu2(add2(qc, kc01.y)));
            fma2(acc[2], pd.y, relu2(add2(qc, kc23.x)));
            fma2(acc[3], pd.y, relu2(add2(qc, kc23.y)));
            fma2(acc[4], pd.y, relu2(add2(qc, kc45.x)));
            fma2(acc[5], pd.y, relu2(add2(qc, kc45.y)));
            fma2(acc[6], pd.y, relu2(add2(qc, kc67.x)));
            fma2(acc[7], pd.y, relu2(add2(qc, kc67.y)));
        }
#pragma unroll
        for (int i = 0; i < 8; i++)
            scpart[(dh * 8 + i) * 256 + jt] = acc[i];
    }
    __syncthreads();

    // ========== masked softmax (warps 0-7, one row each; folds d-halves) ====
    const int warp = tid >> 5, lane = tid & 31;
    if (warp < 8) {
        const int    r    = warp;
        const float* arow = adj + ((size_t)(b * Tt) + i0 + r) * Tt;
        float v[16];
        float m = -3.4e38f;
#pragma unroll
        for (int t = 0; t < 16; t++) {
            int   j = lane + 32 * t;
            float s = scpf[r * Tt + j] + scpf[(8 + r) * Tt + j];
            s    = (arow[j] > 0.f) ? s : NEG_INF;
            v[t] = s;
            m    = fmaxf(m, s);
        }
#pragma unroll
        for (int o = 16; o; o >>= 1) m = fmaxf(m, __shfl_xor_sync(0xffffffff, m, o));
        float sum = 0.f;
#pragma unroll
        for (int t = 0; t < 16; t++) {
            v[t] = __expf(v[t] - m);
            sum += v[t];
        }
#pragma unroll
        for (int o = 16; o; o >>= 1) sum += __shfl_xor_sync(0xffffffff, sum, o);
        float inv = 1.f / sum;
#pragma unroll
        for (int t = 0; t < 16; t++)
            scd[(lane + 32 * t) * SCD_STRIDE + r] = dup2(v[t] * inv);
    }
    __syncthreads();

    // ================= AV: warps = 8 jq x 2 dq; thread = 8i x 2d ===========
    const int jq = warp >> 1;  // 0..7 -> 64 j's
    const int dq = warp & 1;   // 0/1 -> d half
    const int d0 = dq * 64 + 2 * lane;

    u64 av[8];
#pragma unroll
    for (int i = 0; i < 8; i++) av[i] = 0ull;

    const float* xb = x + (size_t)(b * Tt) * Cc;
#pragma unroll 4
    for (int jj = 0; jj < 64; jj++) {
        int        j   = jq * 64 + jj;
        ulonglong2 w01 = *(const ulonglong2*)(scd + j * SCD_STRIDE + 0);
        ulonglong2 w23 = *(const ulonglong2*)(scd + j * SCD_STRIDE + 2);
        ulonglong2 w45 = *(const ulonglong2*)(scd + j * SCD_STRIDE + 4);
        ulonglong2 w67 = *(const ulonglong2*)(scd + j * SCD_STRIDE + 6);
        u64        xv  = *(const u64*)(xb + (size_t)j * Cc + d0);
        fma2(av[0], w01.x, xv);
        fma2(av[1], w01.y, xv);
        fma2(av[2], w23.x, xv);
        fma2(av[3], w23.y, xv);
        fma2(av[4], w45.x, xv);
        fma2(av[5], w45.y, xv);
        fma2(av[6], w67.x, xv);
        fma2(av[7], w67.y, xv);
    }
    __syncthreads();

    // reduce over jq through smem (reuse scpart: 7*8*64 = 3584 u64 <= 4096)
    u64* buf = scpart;
    if (jq != 0) {
#pragma unroll
        for (int i = 0; i < 8; i++)
            buf[((jq - 1) * 8 + i) * 64 + dq * 32 + lane] = av[i];
    }
    __syncthreads();
    if (jq == 0) {
#pragma unroll
        for (int q = 0; q < 7; q++)
#pragma unroll
            for (int i = 0; i < 8; i++)
                av[i] = add2(av[i], buf[(q * 8 + i) * 64 + dq * 32 + lane]);
#pragma unroll
        for (int i = 0; i < 8; i++)
            *(u64*)(out + (size_t)(b * Tt + i0 + i) * Cc + d0) = av[i];
    }
}

// ---------------------------------------------------------------------------
extern "C" void kernel_launch(void* const* d_in, const int* in_sizes, int n_in,
                              void* d_out, int out_size) {
    const float* x   = (const float*)d_in[0];
    const float* adj = (const float*)d_in[1];
    const float* WQ  = (const float*)d_in[2];
    const float* WK  = (const float*)d_in[3];
    const float* p   = (const float*)d_in[4];
    float*       out = (float*)d_out;

    qk_kernel<<<dim3(NROWS / 16, 2), 256>>>(x, WQ, WK);
    tr_kernel<<<dim3(NROWS / 32, Cc / 32), 256>>>();

    cudaFuncSetAttribute(attn_kernel, cudaFuncAttributeMaxDynamicSharedMemorySize,
                         AT_SMEM_BYTES);
    attn_kernel<<<dim3(Tt / TI, Bb), 512, AT_SMEM_BYTES>>>(x, adj, p, out);
}